// round 3
// baseline (speedup 1.0000x reference)
#include <cuda_runtime.h>
#include <math.h>

#define B 1024
#define D 64
#define O 64
#define M 1024
#define DELTA_F 0.13533528323661270f   // exp(-2)

// ------------------------- device scratch (no mallocs) -------------------------
__device__ float g_sen[B];          // ||x_i||^2
__device__ float g_gterm;           // gsm - sum(gm^2)
__device__ int   g_flag;            // 1 => fast-path hypothesis violated -> run scan
__device__ float g_protos[M * D];
__device__ float g_cents [M * D];
__device__ float g_senc[M];
__device__ float g_cc[M];           // sum(cents^2) per rule
__device__ float g_pp[M];           // sum(protos^2) per rule
__device__ int   g_sup[M];
__device__ int   g_n;
__device__ float g_Gt[B * M];       // Gt[i*M + j] = dot(protos_j, x_i)
__device__ float g_lam[B * M];      // lam[i*M + j] = lambda_{j,i}
__device__ float g_yn[B * O];       // sigmoid(x @ W^T + b)

// ------------------------- K1: sen per row (warp per row) -------------------------
__global__ void k_sen(const float* __restrict__ x) {
    int warp = (blockIdx.x * blockDim.x + threadIdx.x) >> 5;
    int lane = threadIdx.x & 31;
    if (warp >= B) return;
    const float* row = x + warp * D;
    float a = row[lane], b = row[lane + 32];
    float s = a * a + b * b;
    #pragma unroll
    for (int o = 16; o > 0; o >>= 1) s += __shfl_down_sync(0xffffffffu, s, o);
    if (lane == 0) g_sen[warp] = s;
}

// ------------------------- K2: g_term, flag reset -------------------------
__global__ void k_gterm(const float* __restrict__ x) {
    __shared__ float part[16][64];
    __shared__ float red[32];
    __shared__ float gsq[64];
    int t = threadIdx.x;          // 1024 threads
    int d = t & 63, g = t >> 6;   // 16 groups of 64 columns
    float s = 0.f;
    for (int r = g; r < B; r += 16) s += x[r * D + d];
    part[g][d] = s;

    // sum of sen (1024 elements, one per thread)
    float ss = g_sen[t];
    #pragma unroll
    for (int o = 16; o > 0; o >>= 1) ss += __shfl_down_sync(0xffffffffu, ss, o);
    if ((t & 31) == 0) red[t >> 5] = ss;
    __syncthreads();
    if (t < 32) {
        float v = red[t];
        #pragma unroll
        for (int o = 16; o > 0; o >>= 1) v += __shfl_down_sync(0xffffffffu, v, o);
        if (t == 0) red[0] = v;
    }
    __syncthreads();
    if (t < 64) {
        float cs = 0.f;
        #pragma unroll
        for (int gg = 0; gg < 16; gg++) cs += part[gg][t];
        float gm = cs / (1048576.0f);         // (colsum/B)/B
        gsq[t] = gm * gm;
    }
    __syncthreads();
    if (t == 0) {
        float sq = 0.f;
        for (int dd = 0; dd < 64; dd++) sq += gsq[dd];
        float gsm = red[0] / 1048576.0f;      // (sensum/B)/B
        g_gterm = gsm - sq;
        g_flag = 0;
        g_n = B;                              // fast-path rule count
    }
}

// ------------------------- K2b: fast-path state init -------------------------
__global__ void k_init_state(const float* __restrict__ x) {
    int k = blockIdx.x * blockDim.x + threadIdx.x;
    if (k < M * D) { float v = x[k]; g_protos[k] = v; g_cents[k] = v; }
    if (k < M) {
        float s = g_sen[k];
        g_senc[k] = s; g_cc[k] = s; g_pp[k] = s; g_sup[k] = 1;
    }
}

// ------------------------- K3: Gram x@x^T + all-create verification -------------------------
// 32x32 tile, 2x2 outputs/thread (strided by 16 for coalesced stores), 1 LDS : 1 FFMA.
__global__ void k_gram_verify(const float* __restrict__ x) {
    __shared__ float xi[32][65];
    __shared__ float xj[32][65];
    int tx = threadIdx.x, ty = threadIdx.y;           // 16x16
    int lt = ty * 16 + tx;
    int i0 = blockIdx.y * 32, j0 = blockIdx.x * 32;
    for (int idx = lt; idx < 32 * 64; idx += 256) {   // 2048 elems, 8 per thread
        int r = idx >> 6, d = idx & 63;
        xi[r][d] = x[(i0 + r) * D + d];
        xj[r][d] = x[(j0 + r) * D + d];
    }
    __syncthreads();
    float acc00 = 0.f, acc01 = 0.f, acc10 = 0.f, acc11 = 0.f;
    #pragma unroll
    for (int d = 0; d < 64; d++) {
        float a0 = xi[ty][d],      a1 = xi[ty + 16][d];
        float b0 = xj[tx][d],      b1 = xj[tx + 16][d];
        acc00 += a0 * b0; acc01 += a0 * b1;
        acc10 += a1 * b0; acc11 += a1 * b1;
    }
    float thr = 3.0f * fabsf(g_gterm);
    int i_a = i0 + ty, i_b = i0 + ty + 16;
    int j_a = j0 + tx, j_b = j0 + tx + 16;
    float sia = g_sen[i_a], sib = g_sen[i_b];
    float sja = g_sen[j_a], sjb = g_sen[j_b];
    g_Gt[i_a * M + j_a] = acc00;
    g_Gt[i_a * M + j_b] = acc01;
    g_Gt[i_b * M + j_a] = acc10;
    g_Gt[i_b * M + j_b] = acc11;
    // verification: with all-create state, stau_j == |g_term|/2; create requires d2 > 2*stau.
    // flag with 3x margin so any borderline pair routes to the exact scan.
    int bad = 0;
    bad |= (i_a != j_a) && (sia + sja - 2.0f * acc00 < thr);
    bad |= (i_a != j_b) && (sia + sjb - 2.0f * acc01 < thr);
    bad |= (i_b != j_a) && (sib + sja - 2.0f * acc10 < thr);
    bad |= (i_b != j_b) && (sib + sjb - 2.0f * acc11 < thr);
    if (bad) atomicOr(&g_flag, 1);
}

// ------------------------- K4: exact sequential scan (fallback, normally skipped) -------------------------
__global__ void __launch_bounds__(1024, 1) k_scan_fallback(const float* __restrict__ x) {
    if (g_flag == 0) return;
    __shared__ float xs[64];
    __shared__ float red_val[32];
    __shared__ int   red_idx[32];
    __shared__ int s_n, s_w, s_create;
    __shared__ float s_sf;
    int t = threadIdx.x;
    if (t == 0) s_n = 0;
    __syncthreads();
    float gterm = g_gterm;
    for (int i = 0; i < B; i++) {
        if (t < 64) xs[t] = x[i * D + t];
        __syncthreads();
        int n = s_n;
        float dens;
        if (t < n) {
            float dist = 0.f;
            #pragma unroll 8
            for (int d = 0; d < 64; d++) { float v = xs[d] - g_protos[t * D + d]; dist += v * v; }
            float stau = fabsf(gterm + g_senc[t] - g_cc[t]) * 0.5f;
            dens = expf(-dist / stau);
        } else dens = -INFINITY;
        float v = dens; int idx = t;
        #pragma unroll
        for (int o = 16; o > 0; o >>= 1) {
            float ov = __shfl_down_sync(0xffffffffu, v, o);
            int   oi = __shfl_down_sync(0xffffffffu, idx, o);
            if (ov > v || (ov == v && oi < idx)) { v = ov; idx = oi; }
        }
        if ((t & 31) == 0) { red_val[t >> 5] = v; red_idx[t >> 5] = idx; }
        __syncthreads();
        if (t < 32) {
            v = red_val[t]; idx = red_idx[t];
            #pragma unroll
            for (int o = 16; o > 0; o >>= 1) {
                float ov = __shfl_down_sync(0xffffffffu, v, o);
                int   oi = __shfl_down_sync(0xffffffffu, idx, o);
                if (ov > v || (ov == v && oi < idx)) { v = ov; idx = oi; }
            }
            if (t == 0) {
                int create = (n == 0) || (v < DELTA_F);
                int w = create ? min(n, M - 1) : idx;
                int supn = create ? 1 : (g_sup[w] + 1);
                g_sup[w] = supn;
                s_w = w; s_create = create; s_sf = (float)supn;
                if (create) s_n = min(n + 1, M);
            }
        }
        __syncthreads();
        int w = s_w; float sf = s_sf; int create = s_create;
        if (t < 64) {
            float xiv = xs[t];
            float p = g_protos[w * D + t];
            float c = g_cents[w * D + t];
            g_protos[w * D + t] = create ? xiv : p;
            g_cents [w * D + t] = create ? xiv : (c + (xiv - c) / sf);
        }
        __syncthreads();
        if (t < 32) {
            float a = g_cents[w * D + t], b2 = g_cents[w * D + t + 32];
            float s = a * a + b2 * b2;
            #pragma unroll
            for (int o = 16; o > 0; o >>= 1) s += __shfl_down_sync(0xffffffffu, s, o);
            if (t == 0) {
                float si = g_sen[i];
                float sc = g_senc[w];
                g_senc[w] = create ? si : (sc + (si - sc) / sf);
                g_cc[w] = s;
            }
        }
        __syncthreads();
    }
    if (t == 0) g_n = s_n;
    __syncthreads();
    // recompute pp and Gt from final protos (slow; only on fallback)
    for (int j = t; j < M; j += 1024) {
        float s = 0.f;
        for (int d = 0; d < 64; d++) { float p = g_protos[j * D + d]; s += p * p; }
        g_pp[j] = s;
    }
    for (int k = t; k < B * M; k += 1024) {
        int i = k >> 10, j = k & (M - 1);
        float s = 0.f;
        for (int d = 0; d < 64; d++) s += g_protos[j * D + d] * x[i * D + d];
        g_Gt[k] = s;
    }
}

// ------------------------- K5: dens -> lambda (block per column i), stau inline -------------------------
__global__ void k_lambda() {
    __shared__ float red[32];
    __shared__ float s_inv;
    int i = blockIdx.x, t = threadIdx.x;       // 256 threads
    float sen_i = g_sen[i];
    float gterm = g_gterm;
    int n = g_n;
    float dv[4];
    float local = 0.f;
    #pragma unroll
    for (int k = 0; k < 4; k++) {
        int j = t + k * 256;
        float stau = fabsf(gterm + g_senc[j] - g_cc[j]) * 0.5f;
        float d2 = sen_i + g_pp[j] - 2.0f * g_Gt[i * M + j];
        d2 = fmaxf(d2, 0.0f);
        float dens = (j < n) ? expf(-d2 / stau) : 0.0f;
        dv[k] = dens;
        local += dens;
    }
    #pragma unroll
    for (int o = 16; o > 0; o >>= 1) local += __shfl_down_sync(0xffffffffu, local, o);
    if ((t & 31) == 0) red[t >> 5] = local;
    __syncthreads();
    if (t < 8) {
        float v = red[t];
        #pragma unroll
        for (int o = 4; o > 0; o >>= 1) v += __shfl_down_sync(0xffu, v, o);
        if (t == 0) s_inv = 1.0f / v;
    }
    __syncthreads();
    float inv = s_inv;
    #pragma unroll
    for (int k = 0; k < 4; k++) g_lam[i * M + t + k * 256] = dv[k] * inv;
}

// ------------------------- K6: y_n = sigmoid(x W^T + b) -------------------------
__global__ void k_yn(const float* __restrict__ x, const float* __restrict__ W,
                     const float* __restrict__ b) {
    __shared__ float xs[64];
    int i = blockIdx.x, o = threadIdx.x;       // 64 threads
    xs[o] = x[i * D + o];
    __syncthreads();
    float z = b[o];
    #pragma unroll
    for (int d = 0; d < 64; d++) z += xs[d] * W[o * D + d];
    g_yn[i * O + o] = 1.0f / (1.0f + expf(-z));
}

// ------------------------- K7: output broadcast write (HBM-store-bound) -------------------------
__global__ void k_out(float4* __restrict__ out) {
    __shared__ float  lam_s[64];
    __shared__ float4 yn_s[16];
    int i = blockIdx.x, c = blockIdx.y, t = threadIdx.x;   // 256 threads, c in [0,16)
    if (t < 64) lam_s[t] = g_lam[i * M + c * 64 + t];
    if (t < 16) yn_s[t] = reinterpret_cast<const float4*>(g_yn)[i * 16 + t];
    __syncthreads();
    float4* dst = out + (size_t)i * 16384 + (size_t)c * 1024;
    #pragma unroll
    for (int k = 0; k < 4; k++) {
        int f = t + k * 256;                 // [0,1024): 1024 float4 per block
        float l = lam_s[f >> 4];
        float4 v = yn_s[f & 15];
        v.x *= l; v.y *= l; v.z *= l; v.w *= l;
        __stcs(dst + f, v);                  // streaming store: write-once data, spare L2
    }
}

// ------------------------- launch -------------------------
extern "C" void kernel_launch(void* const* d_in, const int* in_sizes, int n_in,
                              void* d_out, int out_size) {
    const float* x = (const float*)d_in[0];
    const float* W = (const float*)d_in[1];
    const float* b = (const float*)d_in[2];
    float4* out = (float4*)d_out;

    k_sen<<<B / 8, 256>>>(x);
    k_gterm<<<1, 1024>>>(x);
    k_init_state<<<(M * D + 255) / 256, 256>>>(x);
    k_gram_verify<<<dim3(M / 32, B / 32), dim3(16, 16)>>>(x);
    k_scan_fallback<<<1, 1024>>>(x);
    k_lambda<<<B, 256>>>();
    k_yn<<<B, 64>>>(x, W, b);
    k_out<<<dim3(B, 16), 256>>>(out);
}